// round 2
// baseline (speedup 1.0000x reference)
#include <cuda_runtime.h>
#include <cuda_bf16.h>
#include <cstddef>

// ---------------------------------------------------------------------------
// Problem dims (fixed)
// ---------------------------------------------------------------------------
#define LAYERS 6
#define BATCH  4
#define SEQ    512
#define DMODEL 1024
#define NHEAD  16
#define DHEAD  64
#define DFF    4096
#define ROWS   (BATCH * SEQ)           // 2048
#define BH     (BATCH * NHEAD)         // 64

// ---------------------------------------------------------------------------
// Scratch (device globals; no allocation allowed)
// ---------------------------------------------------------------------------
__device__ float g_x  [ROWS * DMODEL];
__device__ float g_q  [ROWS * DMODEL];
__device__ float g_k  [ROWS * DMODEL];
__device__ float g_v  [ROWS * DMODEL];
__device__ float g_sc [(size_t)BH * SEQ * SEQ];   // scores / attn probs
__device__ float g_ctx[ROWS * DMODEL];
__device__ float g_tmp[ROWS * DMODEL];
__device__ float g_ffn[(size_t)ROWS * DFF];

// ---------------------------------------------------------------------------
// Block reduction helpers
// ---------------------------------------------------------------------------
__device__ __forceinline__ float block_reduce_sum(float v, float* shm) {
    __syncthreads();
    int lane = threadIdx.x & 31, w = threadIdx.x >> 5;
    #pragma unroll
    for (int o = 16; o; o >>= 1) v += __shfl_xor_sync(0xffffffff, v, o);
    if (lane == 0) shm[w] = v;
    __syncthreads();
    int nw = blockDim.x >> 5;
    float r = (threadIdx.x < nw) ? shm[threadIdx.x] : 0.f;
    if (w == 0) {
        #pragma unroll
        for (int o = 16; o; o >>= 1) r += __shfl_xor_sync(0xffffffff, r, o);
        if (lane == 0) shm[0] = r;
    }
    __syncthreads();
    return shm[0];
}

__device__ __forceinline__ float block_reduce_max(float v, float* shm) {
    __syncthreads();
    int lane = threadIdx.x & 31, w = threadIdx.x >> 5;
    #pragma unroll
    for (int o = 16; o; o >>= 1) v = fmaxf(v, __shfl_xor_sync(0xffffffff, v, o));
    if (lane == 0) shm[w] = v;
    __syncthreads();
    int nw = blockDim.x >> 5;
    float r = (threadIdx.x < nw) ? shm[threadIdx.x] : -3.4e38f;
    if (w == 0) {
        #pragma unroll
        for (int o = 16; o; o >>= 1) r = fmaxf(r, __shfl_xor_sync(0xffffffff, r, o));
        if (lane == 0) shm[0] = r;
    }
    __syncthreads();
    return shm[0];
}

// ---------------------------------------------------------------------------
// Embedding: x[b,s,:] = tok_emb[dec[b,s]] + pos_emb[s]
// grid ROWS, block 256
// ---------------------------------------------------------------------------
__global__ void embed_kernel(const int* __restrict__ dec,
                             const float* __restrict__ tok,
                             const float* __restrict__ pos,
                             float* __restrict__ x) {
    int row = blockIdx.x;
    int s   = row & (SEQ - 1);
    int t   = dec[row];
    const float* tp = tok + (size_t)t * DMODEL;
    const float* pp = pos + (size_t)s * DMODEL;
    float* xp = x + (size_t)row * DMODEL;
    #pragma unroll
    for (int u = 0; u < 4; ++u) {
        int c = threadIdx.x + u * 256;
        xp[c] = tp[c] + pp[c];
    }
}

// ---------------------------------------------------------------------------
// SGEMM: C[M,N] = A[M,K] @ B[K,N], optional relu epilogue.
// 128x128 tile, BK=8, 256 threads, 8x8 per-thread micro tile.
// M % 128 == 0, N % 128 == 0, K % 8 == 0.
// ---------------------------------------------------------------------------
__global__ void __launch_bounds__(256) sgemm_kernel(
    const float* __restrict__ A, const float* __restrict__ B,
    float* __restrict__ C, int M, int N, int K, int relu)
{
    __shared__ float As[8][128];
    __shared__ float Bs[8][128];

    const int tid  = threadIdx.x;
    const int bm   = blockIdx.y, bn = blockIdx.x;
    const int aRow = tid >> 1;           // 0..127
    const int aCol = (tid & 1) * 4;      // 0 or 4
    const int bRow = tid >> 5;           // 0..7
    const int bCol = (tid & 31) * 4;     // 0..124
    const int tr   = (tid >> 4) * 8;
    const int tc   = (tid & 15) * 8;

    const float* Ab = A + (size_t)(bm * 128) * K;
    const float* Bb = B + bn * 128;

    float acc[8][8];
    #pragma unroll
    for (int i = 0; i < 8; ++i)
        #pragma unroll
        for (int j = 0; j < 8; ++j) acc[i][j] = 0.f;

    for (int k0 = 0; k0 < K; k0 += 8) {
        float4 av = *(const float4*)(Ab + (size_t)aRow * K + k0 + aCol);
        As[aCol + 0][aRow] = av.x;
        As[aCol + 1][aRow] = av.y;
        As[aCol + 2][aRow] = av.z;
        As[aCol + 3][aRow] = av.w;
        float4 bv = *(const float4*)(Bb + (size_t)(k0 + bRow) * N + bCol);
        *(float4*)(&Bs[bRow][bCol]) = bv;
        __syncthreads();

        #pragma unroll
        for (int kk = 0; kk < 8; ++kk) {
            float ra[8], rb[8];
            #pragma unroll
            for (int i = 0; i < 8; ++i) ra[i] = As[kk][tr + i];
            #pragma unroll
            for (int j = 0; j < 8; ++j) rb[j] = Bs[kk][tc + j];
            #pragma unroll
            for (int i = 0; i < 8; ++i)
                #pragma unroll
                for (int j = 0; j < 8; ++j) acc[i][j] += ra[i] * rb[j];
        }
        __syncthreads();
    }

    #pragma unroll
    for (int i = 0; i < 8; ++i) {
        size_t r = (size_t)(bm * 128 + tr + i) * N + bn * 128 + tc;
        #pragma unroll
        for (int j = 0; j < 8; ++j) {
            float v = acc[i][j];
            if (relu) v = fmaxf(v, 0.f);
            C[r + j] = v;
        }
    }
}

// ---------------------------------------------------------------------------
// Attention scores: scores[bh,q,k] = (Q[b,q,h*64:] . K[b,k,h*64:]) / 8
// grid (S/64, S/64, BH), block 256. 64x64 tile, full K=64.
// ---------------------------------------------------------------------------
__global__ void __launch_bounds__(256) attn_scores_kernel(
    const float* __restrict__ Q, const float* __restrict__ Kt,
    float* __restrict__ scores)
{
    int bh = blockIdx.z;
    int b  = bh >> 4, h = bh & 15;
    int q0 = blockIdx.y * 64, k0 = blockIdx.x * 64;

    __shared__ float Qs[64][68];
    __shared__ float Ks[64][68];

    const float* Qb = Q + (size_t)b * SEQ * DMODEL + h * DHEAD;
    const float* Kb = Kt + (size_t)b * SEQ * DMODEL + h * DHEAD;

    int tid = threadIdx.x;
    int lr = tid >> 4;           // 0..15
    int lc = (tid & 15) * 4;     // 0..60
    #pragma unroll
    for (int rr = 0; rr < 64; rr += 16) {
        *(float4*)&Qs[lr + rr][lc] =
            *(const float4*)(Qb + (size_t)(q0 + lr + rr) * DMODEL + lc);
        *(float4*)&Ks[lr + rr][lc] =
            *(const float4*)(Kb + (size_t)(k0 + lr + rr) * DMODEL + lc);
    }
    __syncthreads();

    int tr = (tid >> 4) * 4, tc = (tid & 15) * 4;
    float acc[4][4];
    #pragma unroll
    for (int i = 0; i < 4; ++i)
        #pragma unroll
        for (int j = 0; j < 4; ++j) acc[i][j] = 0.f;

    #pragma unroll
    for (int kk = 0; kk < 64; ++kk) {
        float ra[4], rb[4];
        #pragma unroll
        for (int i = 0; i < 4; ++i) ra[i] = Qs[tr + i][kk];
        #pragma unroll
        for (int j = 0; j < 4; ++j) rb[j] = Ks[tc + j][kk];
        #pragma unroll
        for (int i = 0; i < 4; ++i)
            #pragma unroll
            for (int j = 0; j < 4; ++j) acc[i][j] += ra[i] * rb[j];
    }

    float* Sb = scores + (size_t)bh * SEQ * SEQ;
    #pragma unroll
    for (int i = 0; i < 4; ++i)
        #pragma unroll
        for (int j = 0; j < 4; ++j)
            Sb[(size_t)(q0 + tr + i) * SEQ + k0 + tc + j] = acc[i][j] * 0.125f;
}

// ---------------------------------------------------------------------------
// Masked softmax over last dim (in-place). grid BH*S blocks, 128 threads.
// masked: score masked if (k > q) || dec[b,k]==0
// ---------------------------------------------------------------------------
__global__ void __launch_bounds__(128) softmax_kernel(
    float* __restrict__ scores, const int* __restrict__ dec, int masked)
{
    __shared__ float shm[32];
    int row = blockIdx.x;               // bh*S + q
    int q   = row & (SEQ - 1);
    int bh  = row >> 9;
    int b   = bh >> 4;
    float* S = scores + (size_t)row * SEQ;
    const int* db = dec + b * SEQ;

    float v[4];
    float mx = -3.4e38f;
    #pragma unroll
    for (int u = 0; u < 4; ++u) {
        int k = threadIdx.x + u * 128;
        float s = S[k];
        if (masked && ((k > q) || (db[k] == 0))) s = -1e9f;
        v[u] = s;
        mx = fmaxf(mx, s);
    }
    mx = block_reduce_max(mx, shm);

    float sum = 0.f;
    #pragma unroll
    for (int u = 0; u < 4; ++u) {
        v[u] = expf(v[u] - mx);
        sum += v[u];
    }
    sum = block_reduce_sum(sum, shm);
    float inv = 1.f / sum;
    #pragma unroll
    for (int u = 0; u < 4; ++u) {
        int k = threadIdx.x + u * 128;
        S[k] = v[u] * inv;
    }
}

// ---------------------------------------------------------------------------
// ctx[b,q,h*64+d] = sum_k attn[bh,q,k] * V[b,k,h*64+d]
// grid (S/64, BH), block 256. 64(q) x 64(d) tile, BK=16.
// ---------------------------------------------------------------------------
__global__ void __launch_bounds__(256) attn_ctx_kernel(
    const float* __restrict__ attn, const float* __restrict__ Vv,
    float* __restrict__ ctx)
{
    int bh = blockIdx.y;
    int b  = bh >> 4, h = bh & 15;
    int q0 = blockIdx.x * 64;

    __shared__ float As[64][17];
    __shared__ float Bs[16][68];

    const float* Ab = attn + (size_t)bh * SEQ * SEQ;
    const float* Vb = Vv + (size_t)b * SEQ * DMODEL + h * DHEAD;

    int tid = threadIdx.x;
    int ar = tid >> 2, ac = (tid & 3) * 4;   // 64 x 16 A tile
    int br = tid >> 4, bc = (tid & 15) * 4;  // 16 x 64 B tile
    int tr = (tid >> 4) * 4, tc = (tid & 15) * 4;

    float acc[4][4];
    #pragma unroll
    for (int i = 0; i < 4; ++i)
        #pragma unroll
        for (int j = 0; j < 4; ++j) acc[i][j] = 0.f;

    for (int k0 = 0; k0 < SEQ; k0 += 16) {
        float4 av = *(const float4*)(Ab + (size_t)(q0 + ar) * SEQ + k0 + ac);
        As[ar][ac + 0] = av.x; As[ar][ac + 1] = av.y;
        As[ar][ac + 2] = av.z; As[ar][ac + 3] = av.w;
        *(float4*)&Bs[br][bc] =
            *(const float4*)(Vb + (size_t)(k0 + br) * DMODEL + bc);
        __syncthreads();

        #pragma unroll
        for (int kk = 0; kk < 16; ++kk) {
            float ra[4], rb[4];
            #pragma unroll
            for (int i = 0; i < 4; ++i) ra[i] = As[tr + i][kk];
            #pragma unroll
            for (int j = 0; j < 4; ++j) rb[j] = Bs[kk][tc + j];
            #pragma unroll
            for (int i = 0; i < 4; ++i)
                #pragma unroll
                for (int j = 0; j < 4; ++j) acc[i][j] += ra[i] * rb[j];
        }
        __syncthreads();
    }

    #pragma unroll
    for (int i = 0; i < 4; ++i)
        #pragma unroll
        for (int j = 0; j < 4; ++j)
            ctx[(size_t)b * SEQ * DMODEL + (size_t)(q0 + tr + i) * DMODEL
                + h * DHEAD + tc + j] = acc[i][j];
}

// ---------------------------------------------------------------------------
// out = LayerNorm(a + r) * g + beta. grid ROWS, block 256. out may alias r.
// ---------------------------------------------------------------------------
__global__ void __launch_bounds__(256) add_ln_kernel(
    const float* __restrict__ a, const float* __restrict__ r,
    const float* __restrict__ g, const float* __restrict__ beta,
    float* __restrict__ out)
{
    __shared__ float shm[32];
    int row = blockIdx.x;
    const float* ap = a + (size_t)row * DMODEL;
    const float* rp = r + (size_t)row * DMODEL;
    float* op = out + (size_t)row * DMODEL;

    float v[4];
    float s = 0.f;
    #pragma unroll
    for (int u = 0; u < 4; ++u) {
        int c = threadIdx.x + u * 256;
        v[u] = ap[c] + rp[c];
        s += v[u];
    }
    float mean = block_reduce_sum(s, shm) * (1.f / DMODEL);

    float sq = 0.f;
    #pragma unroll
    for (int u = 0; u < 4; ++u) {
        float d = v[u] - mean;
        sq += d * d;
    }
    float var = block_reduce_sum(sq, shm) * (1.f / DMODEL);
    float rstd = rsqrtf(var + 1e-5f);

    #pragma unroll
    for (int u = 0; u < 4; ++u) {
        int c = threadIdx.x + u * 256;
        op[c] = (v[u] - mean) * rstd * g[c] + beta[c];
    }
}

// ---------------------------------------------------------------------------
// Host orchestration
// ---------------------------------------------------------------------------
static void run_sgemm(const float* A, const float* B, float* C,
                      int M, int N, int K, int relu) {
    dim3 grid(N / 128, M / 128);
    sgemm_kernel<<<grid, 256>>>(A, B, C, M, N, K, relu);
}

extern "C" void kernel_launch(void* const* d_in, const int* in_sizes, int n_in,
                              void* d_out, int out_size) {
    const int*   dec  = (const int*)  d_in[0];
    const float* tok  = (const float*)d_in[1];
    const float* pos  = (const float*)d_in[2];
    const float* Wq1  = (const float*)d_in[3];
    const float* Wk1  = (const float*)d_in[4];
    const float* Wv1  = (const float*)d_in[5];
    const float* Wo1  = (const float*)d_in[6];
    const float* g1   = (const float*)d_in[7];
    const float* b1   = (const float*)d_in[8];
    const float* Wq2  = (const float*)d_in[9];
    const float* Wk2  = (const float*)d_in[10];
    const float* Wv2  = (const float*)d_in[11];
    const float* Wo2  = (const float*)d_in[12];
    const float* g2   = (const float*)d_in[13];
    const float* b2   = (const float*)d_in[14];
    const float* Wff1 = (const float*)d_in[15];
    const float* Wff2 = (const float*)d_in[16];
    const float* gff  = (const float*)d_in[17];
    const float* bff  = (const float*)d_in[18];
    float* out = (float*)d_out;

    float *x, *q, *k, *v, *sc, *ctx, *tmp, *ffn;
    cudaGetSymbolAddress((void**)&x,   g_x);
    cudaGetSymbolAddress((void**)&q,   g_q);
    cudaGetSymbolAddress((void**)&k,   g_k);
    cudaGetSymbolAddress((void**)&v,   g_v);
    cudaGetSymbolAddress((void**)&sc,  g_sc);
    cudaGetSymbolAddress((void**)&ctx, g_ctx);
    cudaGetSymbolAddress((void**)&tmp, g_tmp);
    cudaGetSymbolAddress((void**)&ffn, g_ffn);

    const size_t WPROJ = (size_t)DMODEL * DMODEL;   // 1024*1024
    const size_t WF1   = (size_t)DMODEL * DFF;
    const size_t WF2   = (size_t)DFF * DMODEL;
    const size_t ATTN_SZ = (size_t)BH * SEQ * SEQ;  // per-layer attn elements

    embed_kernel<<<ROWS, 256>>>(dec, tok, pos, x);

    dim3 sc_grid(SEQ / 64, SEQ / 64, BH);
    dim3 ctx_grid(SEQ / 64, BH);

    for (int i = 0; i < LAYERS; ++i) {
        // ---- MHA1 (masked self-attention) ----
        run_sgemm(x, Wq1 + i * WPROJ, q, ROWS, DMODEL, DMODEL, 0);
        run_sgemm(x, Wk1 + i * WPROJ, k, ROWS, DMODEL, DMODEL, 0);
        run_sgemm(x, Wv1 + i * WPROJ, v, ROWS, DMODEL, DMODEL, 0);
        attn_scores_kernel<<<sc_grid, 256>>>(q, k, sc);
        softmax_kernel<<<BH * SEQ, 128>>>(sc, dec, 1);
        attn_ctx_kernel<<<ctx_grid, 256>>>(sc, v, ctx);
        run_sgemm(ctx, Wo1 + i * WPROJ, tmp, ROWS, DMODEL, DMODEL, 0);
        add_ln_kernel<<<ROWS, 256>>>(tmp, x, g1 + i * DMODEL, b1 + i * DMODEL, x);

        // ---- MHA2 (unmasked) ----
        run_sgemm(x, Wq2 + i * WPROJ, q, ROWS, DMODEL, DMODEL, 0);
        run_sgemm(x, Wk2 + i * WPROJ, k, ROWS, DMODEL, DMODEL, 0);
        run_sgemm(x, Wv2 + i * WPROJ, v, ROWS, DMODEL, DMODEL, 0);
        attn_scores_kernel<<<sc_grid, 256>>>(q, k, sc);
        softmax_kernel<<<BH * SEQ, 128>>>(sc, dec, 0);
        // attn probs for this layer go straight to output
        cudaMemcpyAsync(out + (size_t)ROWS * DMODEL + (size_t)i * ATTN_SZ,
                        sc, ATTN_SZ * sizeof(float),
                        cudaMemcpyDeviceToDevice, 0);
        attn_ctx_kernel<<<ctx_grid, 256>>>(sc, v, ctx);
        run_sgemm(ctx, Wo2 + i * WPROJ, tmp, ROWS, DMODEL, DMODEL, 0);
        add_ln_kernel<<<ROWS, 256>>>(tmp, x, g2 + i * DMODEL, b2 + i * DMODEL, x);

        // ---- FFN ----
        run_sgemm(x, Wff1 + i * WF1, ffn, ROWS, DFF, DMODEL, 1);       // relu
        run_sgemm(ffn, Wff2 + i * WF2, tmp, ROWS, DMODEL, DFF, 0);
        add_ln_kernel<<<ROWS, 256>>>(tmp, x, gff + i * DMODEL, bff + i * DMODEL, x);
    }

    cudaMemcpyAsync(out, x, (size_t)ROWS * DMODEL * sizeof(float),
                    cudaMemcpyDeviceToDevice, 0);
}

// round 4
// speedup vs baseline: 2.2619x; 2.2619x over previous
#include <cuda_runtime.h>
#include <cuda_bf16.h>
#include <cstdint>
#include <cstddef>

// ---------------------------------------------------------------------------
// Problem dims (fixed)
// ---------------------------------------------------------------------------
#define LAYERS 6
#define BATCH  4
#define SEQ    512
#define DMODEL 1024
#define NHEAD  16
#define DHEAD  64
#define DFF    4096
#define ROWS   (BATCH * SEQ)           // 2048
#define BH     (BATCH * NHEAD)         // 64

// ---------------------------------------------------------------------------
// Scratch (device globals; no allocation allowed)
// ---------------------------------------------------------------------------
__device__ float g_x  [ROWS * DMODEL];
__device__ float g_q  [ROWS * DMODEL];
__device__ float g_k  [ROWS * DMODEL];
__device__ float g_v  [ROWS * DMODEL];
__device__ float g_sc [(size_t)BH * SEQ * SEQ];   // scores / attn probs
__device__ float g_ctx[ROWS * DMODEL];
__device__ float g_tmp[ROWS * DMODEL];
__device__ float g_ffn[(size_t)ROWS * DFF];

// bf16 split buffers
#define PROJ_T (1024 * 1024)                       // per-layer proj tensor elems
#define W_TOTAL ((size_t)96 * PROJ_T)              // all weights, transposed
__device__ __nv_bfloat16 g_wh[W_TOTAL];
__device__ __nv_bfloat16 g_wl[W_TOTAL];
__device__ __nv_bfloat16 g_ah[(size_t)ROWS * DFF];  // activation hi (max M*K)
__device__ __nv_bfloat16 g_al[(size_t)ROWS * DFF];  // activation lo

// weight offsets (elements) inside g_wh/g_wl
#define OFF_Q1  ((size_t)0 * PROJ_T)
#define OFF_K1  ((size_t)6 * PROJ_T)
#define OFF_V1  ((size_t)12 * PROJ_T)
#define OFF_O1  ((size_t)18 * PROJ_T)
#define OFF_Q2  ((size_t)24 * PROJ_T)
#define OFF_K2  ((size_t)30 * PROJ_T)
#define OFF_V2  ((size_t)36 * PROJ_T)
#define OFF_O2  ((size_t)42 * PROJ_T)
#define OFF_F1  ((size_t)48 * PROJ_T)
#define OFF_F2  ((size_t)72 * PROJ_T)

// ---------------------------------------------------------------------------
// PTX helpers (arch-neutral: cp.async / ldmatrix / mma.sync only)
// ---------------------------------------------------------------------------
__device__ __forceinline__ uint32_t smem_u32(const void* p) {
    uint32_t a;
    asm("{ .reg .u64 t; cvta.to.shared.u64 t, %1; cvt.u32.u64 %0, t; }"
        : "=r"(a) : "l"(p));
    return a;
}
__device__ __forceinline__ void cp16(uint32_t dst, const void* src) {
    asm volatile("cp.async.cg.shared.global [%0], [%1], 16;"
                 :: "r"(dst), "l"(src) : "memory");
}
#define CP_COMMIT() asm volatile("cp.async.commit_group;" ::: "memory")
#define CP_WAIT(n)  asm volatile("cp.async.wait_group %0;" :: "n"(n) : "memory")

__device__ __forceinline__ void ldsm_x4(uint32_t a[4], uint32_t addr) {
    asm volatile("ldmatrix.sync.aligned.m8n8.x4.shared.b16 {%0,%1,%2,%3}, [%4];"
                 : "=r"(a[0]), "=r"(a[1]), "=r"(a[2]), "=r"(a[3]) : "r"(addr));
}
__device__ __forceinline__ void ldsm_x2(uint32_t a[2], uint32_t addr) {
    asm volatile("ldmatrix.sync.aligned.m8n8.x2.shared.b16 {%0,%1}, [%2];"
                 : "=r"(a[0]), "=r"(a[1]) : "r"(addr));
}
__device__ __forceinline__ void mma_bf16(float c[4], const uint32_t a[4],
                                         const uint32_t b[2]) {
    asm volatile("mma.sync.aligned.m16n8k16.row.col.f32.bf16.bf16.f32 "
                 "{%0,%1,%2,%3}, {%4,%5,%6,%7}, {%8,%9}, {%0,%1,%2,%3};"
                 : "+f"(c[0]), "+f"(c[1]), "+f"(c[2]), "+f"(c[3])
                 : "r"(a[0]), "r"(a[1]), "r"(a[2]), "r"(a[3]),
                   "r"(b[0]), "r"(b[1]));
}

// ---------------------------------------------------------------------------
// bf16-split GEMM: C[M,N] = (Ah+Al)[M,K] @ (Bh+Bl)[N,K]^T   (3-term)
// BM=128, BN=128, BK=32, 256 threads, 3-stage cp.async pipeline.
// SMEM tiles: 128 rows x 64B data, 80B pitch (conflict-free ldmatrix).
// ---------------------------------------------------------------------------
#define BKC      32
#define APITCH   80
#define TILE_B   (128 * APITCH)        // 10240
#define STG_B    (4 * TILE_B)          // 40960
#define NSTAGE   3
#define GEMM_SMEM (NSTAGE * STG_B)     // 122880

#define OFF_TAH 0
#define OFF_TAL TILE_B
#define OFF_TBH (2 * TILE_B)
#define OFF_TBL (3 * TILE_B)

__global__ void __launch_bounds__(256, 1)
mm_gemm_kernel(const __nv_bfloat16* __restrict__ Ah,
               const __nv_bfloat16* __restrict__ Al,
               const __nv_bfloat16* __restrict__ Bh,   // [N,K]
               const __nv_bfloat16* __restrict__ Bl,   // [N,K]
               float* __restrict__ C, int M, int N, int K, int relu)
{
    extern __shared__ char smem[];
    const uint32_t sb = smem_u32(smem);
    const int tid  = threadIdx.x;
    const int wid  = tid >> 5, lane = tid & 31;
    const int wm   = wid >> 2;            // 0..1 -> 64-row slab
    const int wn   = wid & 3;             // 0..3 -> 32-col slab
    const int m0   = blockIdx.y * 128, n0 = blockIdx.x * 128;

    // load mapping: 2 x 16B chunks per thread per tile
    const int r0 = (tid * 2) >> 2;        // row of first chunk
    const int c0 = (tid * 2) & 3;         // chunk col of first chunk (then c0+1)

    float acc[4][4][4];
    #pragma unroll
    for (int i = 0; i < 4; ++i)
        #pragma unroll
        for (int j = 0; j < 4; ++j)
            #pragma unroll
            for (int t = 0; t < 4; ++t) acc[i][j][t] = 0.f;

    const int NCHUNK = K / BKC;

    // ---- stage loader ----
    auto load_stage = [&](int stage, int chunk) {
        const uint32_t st = sb + stage * STG_B;
        const int k0 = chunk * BKC;
        #pragma unroll
        for (int u = 0; u < 2; ++u) {
            const int r = r0 + ((c0 + u) >> 2) * 0;  // same row; chunks consecutive
            const int c = c0 + u;
            // (tid*2, tid*2+1) are consecutive -> same row r0, cols c0, c0+1 (c0 in {0,2})
            const uint32_t so = (uint32_t)(r * APITCH + c * 16);
            const size_t   ga = (size_t)(m0 + r) * K + k0 + c * 8;
            const size_t   gb = (size_t)(n0 + r) * K + k0 + c * 8;
            cp16(st + OFF_TAH + so, Ah + ga);
            cp16(st + OFF_TAL + so, Al + ga);
            cp16(st + OFF_TBH + so, Bh + gb);
            cp16(st + OFF_TBL + so, Bl + gb);
        }
    };

    // prologue: stages 0..NSTAGE-2
    load_stage(0, 0); CP_COMMIT();
    load_stage(1, 1); CP_COMMIT();

    for (int ch = 0; ch < NCHUNK; ++ch) {
        CP_WAIT(1);
        __syncthreads();

        // issue next chunk into the stage freed at ch-1
        if (ch + NSTAGE - 1 < NCHUNK)
            load_stage((ch + NSTAGE - 1) % NSTAGE, ch + NSTAGE - 1);
        CP_COMMIT();

        // ---- compute current stage ----
        const uint32_t st  = sb + (ch % NSTAGE) * STG_B;
        const uint32_t bAh = st + OFF_TAH, bBh = st + OFF_TBH;

        #pragma unroll
        for (int ks = 0; ks < 2; ++ks) {
            const int kb = ks * 32;   // byte offset (16 bf16)

            uint32_t fbh[4][2], fbl[4][2];
            #pragma unroll
            for (int nt = 0; nt < 4; ++nt) {
                uint32_t addr = bBh
                    + (uint32_t)((wn * 32 + nt * 8 + (lane & 7)) * APITCH
                                 + kb + ((lane >> 3) & 1) * 16);
                ldsm_x2(fbh[nt], addr);
                ldsm_x2(fbl[nt], addr + TILE_B);
            }

            #pragma unroll
            for (int mt = 0; mt < 4; ++mt) {
                uint32_t addr = bAh
                    + (uint32_t)((wm * 64 + mt * 16 + (lane & 15)) * APITCH
                                 + kb + (lane >> 4) * 16);
                uint32_t fah[4], fal[4];
                ldsm_x4(fah, addr);
                ldsm_x4(fal, addr + TILE_B);
                #pragma unroll
                for (int nt = 0; nt < 4; ++nt) {
                    mma_bf16(acc[mt][nt], fah, fbh[nt]);
                    mma_bf16(acc[mt][nt], fah, fbl[nt]);
                    mma_bf16(acc[mt][nt], fal, fbh[nt]);
                }
            }
        }
        __syncthreads();
    }

    // ---- epilogue ----
    const int rbase = m0 + wm * 64 + (lane >> 2);
    const int cbase = n0 + wn * 32 + (lane & 3) * 2;
    #pragma unroll
    for (int mt = 0; mt < 4; ++mt) {
        #pragma unroll
        for (int nt = 0; nt < 4; ++nt) {
            float* c = acc[mt][nt];
            if (relu) {
                c[0] = fmaxf(c[0], 0.f); c[1] = fmaxf(c[1], 0.f);
                c[2] = fmaxf(c[2], 0.f); c[3] = fmaxf(c[3], 0.f);
            }
            const int rr = rbase + mt * 16;
            const int cc = cbase + nt * 8;
            *(float2*)(C + (size_t)rr * N + cc)       = make_float2(c[0], c[1]);
            *(float2*)(C + (size_t)(rr + 8) * N + cc) = make_float2(c[2], c[3]);
        }
    }
}

// ---------------------------------------------------------------------------
// fp32 -> bf16 hi/lo split (elementwise, vectorized x4)
// ---------------------------------------------------------------------------
__global__ void __launch_bounds__(256) conv_split_kernel(
    const float* __restrict__ A, __nv_bfloat16* __restrict__ H,
    __nv_bfloat16* __restrict__ L, size_t n)
{
    size_t idx = ((size_t)blockIdx.x * 256 + threadIdx.x) * 4;
    if (idx >= n) return;
    float4 a = *(const float4*)(A + idx);
    __nv_bfloat16 hs[4], ls[4];
    float av[4] = { a.x, a.y, a.z, a.w };
    #pragma unroll
    for (int i = 0; i < 4; ++i) {
        hs[i] = __float2bfloat16_rn(av[i]);
        ls[i] = __float2bfloat16_rn(av[i] - __bfloat162float(hs[i]));
    }
    *(uint2*)(H + idx) = *(uint2*)hs;
    *(uint2*)(L + idx) = *(uint2*)ls;
}

// ---------------------------------------------------------------------------
// Weight transpose + split: W[l][K][N] fp32 -> out[l][N][K] bf16 hi/lo
// ---------------------------------------------------------------------------
__global__ void __launch_bounds__(256) convT_split_kernel(
    const float* __restrict__ W, __nv_bfloat16* __restrict__ H,
    __nv_bfloat16* __restrict__ L, int K, int N)
{
    __shared__ float t[32][33];
    const size_t lofs = (size_t)blockIdx.z * K * N;
    const float* Wl = W + lofs;
    const int n0 = blockIdx.x * 32, k0 = blockIdx.y * 32;
    const int tx = threadIdx.x, ty = threadIdx.y;
    #pragma unroll
    for (int i = 0; i < 32; i += 8)
        t[ty + i][tx] = Wl[(size_t)(k0 + ty + i) * N + n0 + tx];
    __syncthreads();
    #pragma unroll
    for (int i = 0; i < 32; i += 8) {
        float v = t[tx][ty + i];             // = W[k0+tx][n0+ty+i]
        __nv_bfloat16 h = __float2bfloat16_rn(v);
        __nv_bfloat16 l = __float2bfloat16_rn(v - __bfloat162float(h));
        size_t o = lofs + (size_t)(n0 + ty + i) * K + k0 + tx;
        H[o] = h; L[o] = l;
    }
}

// ---------------------------------------------------------------------------
// Block reductions
// ---------------------------------------------------------------------------
__device__ __forceinline__ float block_reduce_sum(float v, float* shm) {
    __syncthreads();
    int lane = threadIdx.x & 31, w = threadIdx.x >> 5;
    #pragma unroll
    for (int o = 16; o; o >>= 1) v += __shfl_xor_sync(0xffffffff, v, o);
    if (lane == 0) shm[w] = v;
    __syncthreads();
    int nw = blockDim.x >> 5;
    float r = (threadIdx.x < nw) ? shm[threadIdx.x] : 0.f;
    if (w == 0) {
        #pragma unroll
        for (int o = 16; o; o >>= 1) r += __shfl_xor_sync(0xffffffff, r, o);
        if (lane == 0) shm[0] = r;
    }
    __syncthreads();
    return shm[0];
}
__device__ __forceinline__ float block_reduce_max(float v, float* shm) {
    __syncthreads();
    int lane = threadIdx.x & 31, w = threadIdx.x >> 5;
    #pragma unroll
    for (int o = 16; o; o >>= 1) v = fmaxf(v, __shfl_xor_sync(0xffffffff, v, o));
    if (lane == 0) shm[w] = v;
    __syncthreads();
    int nw = blockDim.x >> 5;
    float r = (threadIdx.x < nw) ? shm[threadIdx.x] : -3.4e38f;
    if (w == 0) {
        #pragma unroll
        for (int o = 16; o; o >>= 1) r = fmaxf(r, __shfl_xor_sync(0xffffffff, r, o));
        if (lane == 0) shm[0] = r;
    }
    __syncthreads();
    return shm[0];
}

// ---------------------------------------------------------------------------
// Embedding
// ---------------------------------------------------------------------------
__global__ void embed_kernel(const int* __restrict__ dec,
                             const float* __restrict__ tok,
                             const float* __restrict__ pos,
                             float* __restrict__ x) {
    int row = blockIdx.x;
    int s   = row & (SEQ - 1);
    int t   = dec[row];
    const float* tp = tok + (size_t)t * DMODEL;
    const float* pp = pos + (size_t)s * DMODEL;
    float* xp = x + (size_t)row * DMODEL;
    #pragma unroll
    for (int u = 0; u < 4; ++u) {
        int c = threadIdx.x + u * 256;
        xp[c] = tp[c] + pp[c];
    }
}

// ---------------------------------------------------------------------------
// Attention scores (fp32): scores[bh,q,k] = Q.K / 8
// ---------------------------------------------------------------------------
__global__ void __launch_bounds__(256) attn_scores_kernel(
    const float* __restrict__ Q, const float* __restrict__ Kt,
    float* __restrict__ scores)
{
    int bh = blockIdx.z;
    int b  = bh >> 4, h = bh & 15;
    int q0 = blockIdx.y * 64, k0 = blockIdx.x * 64;

    __shared__ float Qs[64][68];
    __shared__ float Ks[64][68];

    const float* Qb = Q + (size_t)b * SEQ * DMODEL + h * DHEAD;
    const float* Kb = Kt + (size_t)b * SEQ * DMODEL + h * DHEAD;

    int tid = threadIdx.x;
    int lr = tid >> 4;
    int lc = (tid & 15) * 4;
    #pragma unroll
    for (int rr = 0; rr < 64; rr += 16) {
        *(float4*)&Qs[lr + rr][lc] =
            *(const float4*)(Qb + (size_t)(q0 + lr + rr) * DMODEL + lc);
        *(float4*)&Ks[lr + rr][lc] =
            *(const float4*)(Kb + (size_t)(k0 + lr + rr) * DMODEL + lc);
    }
    __syncthreads();

    int tr = (tid >> 4) * 4, tc = (tid & 15) * 4;
    float acc[4][4];
    #pragma unroll
    for (int i = 0; i < 4; ++i)
        #pragma unroll
        for (int j = 0; j < 4; ++j) acc[i][j] = 0.f;

    #pragma unroll
    for (int kk = 0; kk < 64; ++kk) {
        float ra[4], rb[4];
        #pragma unroll
        for (int i = 0; i < 4; ++i) ra[i] = Qs[tr + i][kk];
        #pragma unroll
        for (int j = 0; j < 4; ++j) rb[j] = Ks[tc + j][kk];
        #pragma unroll
        for (int i = 0; i < 4; ++i)
            #pragma unroll
            for (int j = 0; j < 4; ++j) acc[i][j] += ra[i] * rb[j];
    }

    float* Sb = scores + (size_t)bh * SEQ * SEQ;
    #pragma unroll
    for (int i = 0; i < 4; ++i)
        #pragma unroll
        for (int j = 0; j < 4; ++j)
            Sb[(size_t)(q0 + tr + i) * SEQ + k0 + tc + j] = acc[i][j] * 0.125f;
}

// ---------------------------------------------------------------------------
// Masked softmax (in-place)
// ---------------------------------------------------------------------------
__global__ void __launch_bounds__(128) softmax_kernel(
    float* __restrict__ scores, const int* __restrict__ dec, int masked)
{
    __shared__ float shm[32];
    int row = blockIdx.x;
    int q   = row & (SEQ - 1);
    int bh  = row >> 9;
    int b   = bh >> 4;
    float* S = scores + (size_t)row * SEQ;
    const int* db = dec + b * SEQ;

    float v[4];
    float mx = -3.4e38f;
    #pragma unroll
    for (int u = 0; u < 4; ++u) {
        int k = threadIdx.x + u * 128;
        float s = S[k];
        if (masked && ((k > q) || (db[k] == 0))) s = -1e9f;
        v[u] = s;
        mx = fmaxf(mx, s);
    }
    mx = block_reduce_max(mx, shm);

    float sum = 0.f;
    #pragma unroll
    for (int u = 0; u < 4; ++u) {
        v[u] = expf(v[u] - mx);
        sum += v[u];
    }
    sum = block_reduce_sum(sum, shm);
    float inv = 1.f / sum;
    #pragma unroll
    for (int u = 0; u < 4; ++u) {
        int k = threadIdx.x + u * 128;
        S[k] = v[u] * inv;
    }
}

// ---------------------------------------------------------------------------
// attn @ V (fp32)
// ---------------------------------------------------------------------------
__global__ void __launch_bounds__(256) attn_ctx_kernel(
    const float* __restrict__ attn, const float* __restrict__ Vv,
    float* __restrict__ ctx)
{
    int bh = blockIdx.y;
    int b  = bh >> 4, h = bh & 15;
    int q0 = blockIdx.x * 64;

    __shared__ float As[64][17];
    __shared__ float Bs[16][68];

    const float* Ab = attn + (size_t)bh * SEQ * SEQ;
    const float* Vb = Vv + (size_t)b * SEQ * DMODEL + h * DHEAD;

    int tid = threadIdx.x;
    int ar = tid >> 2, ac = (tid & 3) * 4;
    int br = tid >> 4, bc = (tid & 15) * 4;
    int tr = (tid >> 4) * 4, tc = (tid & 15) * 4;

    float acc[4][4];
    #pragma unroll
    for (int i = 0; i < 4; ++i)
        #pragma unroll
        for (int j = 0; j < 4; ++j) acc[i][j] = 0.f;

    for (int k0 = 0; k0 < SEQ; k0 += 16) {
        float4 av = *(const float4*)(Ab + (size_t)(q0 + ar) * SEQ + k0 + ac);
        As[ar][ac + 0] = av.x; As[ar][ac + 1] = av.y;
        As[ar][ac + 2] = av.z; As[ar][ac + 3] = av.w;
        *(float4*)&Bs[br][bc] =
            *(const float4*)(Vb + (size_t)(k0 + br) * DMODEL + bc);
        __syncthreads();

        #pragma unroll
        for (int kk = 0; kk < 16; ++kk) {
            float ra[4], rb[4];
            #pragma unroll
            for (int i = 0; i < 4; ++i) ra[i] = As[tr + i][kk];
            #pragma unroll
            for (int j = 0; j < 4; ++j) rb[j] = Bs[kk][tc + j];
            #pragma unroll
            for (int i = 0; i < 4; ++i)
                #pragma unroll
                for (int j = 0; j < 4; ++j) acc[i][j] += ra[i] * rb[j];
        }
        __syncthreads();
    }

    #pragma unroll
    for (int i = 0; i < 4; ++i)
        #pragma unroll
        for (int j = 0; j < 4; ++j)
            ctx[(size_t)b * SEQ * DMODEL + (size_t)(q0 + tr + i) * DMODEL
                + h * DHEAD + tc + j] = acc[i][j];
}

// ---------------------------------------------------------------------------
// out = LayerNorm(a + r) * g + beta
// ---------------------------------------------------------------------------
__global__ void __launch_bounds__(256) add_ln_kernel(
    const float* __restrict__ a, const float* __restrict__ r,
    const float* __restrict__ g, const float* __restrict__ beta,
    float* __restrict__ out)
{
    __shared__ float shm[32];
    int row = blockIdx.x;
    const float* ap = a + (size_t)row * DMODEL;
    const float* rp = r + (size_t)row * DMODEL;
    float* op = out + (size_t)row * DMODEL;

    float v[4];
    float s = 0.f;
    #pragma unroll
    for (int u = 0; u < 4; ++u) {
        int c = threadIdx.x + u * 256;
        v[u] = ap[c] + rp[c];
        s += v[u];
    }
    float mean = block_reduce_sum(s, shm) * (1.f / DMODEL);

    float sq = 0.f;
    #pragma unroll
    for (int u = 0; u < 4; ++u) {
        float d = v[u] - mean;
        sq += d * d;
    }
    float var = block_reduce_sum(sq, shm) * (1.f / DMODEL);
    float rstd = rsqrtf(var + 1e-5f);

    #pragma unroll
    for (int u = 0; u < 4; ++u) {
        int c = threadIdx.x + u * 256;
        op[c] = (v[u] - mean) * rstd * g[c] + beta[c];
    }
}

// ---------------------------------------------------------------------------
// Host orchestration
// ---------------------------------------------------------------------------
static void mm_gemm(const __nv_bfloat16* ah, const __nv_bfloat16* al,
                    const __nv_bfloat16* bh, const __nv_bfloat16* bl,
                    float* C, int M, int N, int K, int relu) {
    dim3 grid(N / 128, M / 128);
    mm_gemm_kernel<<<grid, 256, GEMM_SMEM>>>(ah, al, bh, bl, C, M, N, K, relu);
}

static void conv_split(const float* A, __nv_bfloat16* H, __nv_bfloat16* L, size_t n) {
    conv_split_kernel<<<(unsigned)(n / 1024), 256>>>(A, H, L, n);
}

extern "C" void kernel_launch(void* const* d_in, const int* in_sizes, int n_in,
                              void* d_out, int out_size) {
    const int*   dec  = (const int*)  d_in[0];
    const float* tok  = (const float*)d_in[1];
    const float* pos  = (const float*)d_in[2];
    const float* Wq1  = (const float*)d_in[3];
    const float* Wk1  = (const float*)d_in[4];
    const float* Wv1  = (const float*)d_in[5];
    const float* Wo1  = (const float*)d_in[6];
    const float* g1   = (const float*)d_in[7];
    const float* b1   = (const float*)d_in[8];
    const float* Wq2  = (const float*)d_in[9];
    const float* Wk2  = (const float*)d_in[10];
    const float* Wv2  = (const float*)d_in[11];
    const float* Wo2  = (const float*)d_in[12];
    const float* g2   = (const float*)d_in[13];
    const float* b2   = (const float*)d_in[14];
    const float* Wff1 = (const float*)d_in[15];
    const float* Wff2 = (const float*)d_in[16];
    const float* gff  = (const float*)d_in[17];
    const float* bff  = (const float*)d_in[18];
    float* out = (float*)d_out;

    cudaFuncSetAttribute(mm_gemm_kernel,
                         cudaFuncAttributeMaxDynamicSharedMemorySize, GEMM_SMEM);

    float *x, *q, *k, *v, *sc, *ctx, *tmp, *ffn;
    __nv_bfloat16 *wh, *wl, *ah, *al;
    cudaGetSymbolAddress((void**)&x,   g_x);
    cudaGetSymbolAddress((void**)&q,   g_q);
    cudaGetSymbolAddress((void**)&k,   g_k);
    cudaGetSymbolAddress((void**)&v,   g_v);
    cudaGetSymbolAddress((void**)&sc,  g_sc);
    cudaGetSymbolAddress((void**)&ctx, g_ctx);
    cudaGetSymbolAddress((void**)&tmp, g_tmp);
    cudaGetSymbolAddress((void**)&ffn, g_ffn);
    cudaGetSymbolAddress((void**)&wh,  g_wh);
    cudaGetSymbolAddress((void**)&wl,  g_wl);
    cudaGetSymbolAddress((void**)&ah,  g_ah);
    cudaGetSymbolAddress((void**)&al,  g_al);

    // ---- weight transpose + split (all layers) ----
    dim3 tb(32, 8);
    convT_split_kernel<<<dim3(32, 32, LAYERS),  tb>>>(Wq1,  wh + OFF_Q1, wl + OFF_Q1, 1024, 1024);
    convT_split_kernel<<<dim3(32, 32, LAYERS),  tb>>>(Wk1,  wh + OFF_K1, wl + OFF_K1, 1024, 1024);
    convT_split_kernel<<<dim3(32, 32, LAYERS),  tb>>>(Wv1,  wh + OFF_V1, wl + OFF_V1, 1024, 1024);
    convT_split_kernel<<<dim3(32, 32, LAYERS),  tb>>>(Wo1,  wh + OFF_O1, wl + OFF_O1, 1024, 1024);
    convT_split_kernel<<<dim3(32, 32, LAYERS),  tb>>>(Wq2,  wh + OFF_Q2, wl + OFF_Q2, 1024, 1024);
    convT_split_kernel<<<dim3(32, 32, LAYERS),  tb>>>(Wk2,  wh + OFF_K2, wl + OFF_K2, 1024, 1024);
    convT_split_kernel<<<dim3(32, 32, LAYERS),  tb>>>(Wv2,  wh + OFF_V2, wl + OFF_V2, 1024, 1024);
    convT_split_kernel<<<dim3(32, 32, LAYERS),  tb>>>(Wo2,  wh + OFF_O2, wl + OFF_O2, 1024, 1024);
    convT_split_kernel<<<dim3(128, 32, LAYERS), tb>>>(Wff1, wh + OFF_F1, wl + OFF_F1, 1024, 4096);
    convT_split_kernel<<<dim3(32, 128, LAYERS), tb>>>(Wff2, wh + OFF_F2, wl + OFF_F2, 4096, 1024);

    const size_t ATTN_SZ = (size_t)BH * SEQ * SEQ;
    const size_t XN = (size_t)ROWS * DMODEL;

    embed_kernel<<<ROWS, 256>>>(dec, tok, pos, x);

    dim3 sc_grid(SEQ / 64, SEQ / 64, BH);
    dim3 ctx_grid(SEQ / 64, BH);

    for (int i = 0; i < LAYERS; ++i) {
        const size_t lp = (size_t)i * PROJ_T;     // per-layer proj offset
        const size_t lf = (size_t)i * 4 * PROJ_T; // per-layer ffn offset

        // ---- MHA1 (masked) ----
        conv_split(x, ah, al, XN);
        mm_gemm(ah, al, wh + OFF_Q1 + lp, wl + OFF_Q1 + lp, q, ROWS, DMODEL, DMODEL, 0);
        mm_gemm(ah, al, wh + OFF_K1 + lp, wl + OFF_K1 + lp, k, ROWS, DMODEL, DMODEL, 0);
        mm_gemm(ah, al, wh + OFF_V1 + lp, wl + OFF_V1 + lp, v, ROWS, DMODEL, DMODEL, 0);
        attn_scores_kernel<<<sc_grid, 256>>>(q, k, sc);
        softmax_kernel<<<BH * SEQ, 128>>>(sc, dec, 1);
        attn_ctx_kernel<<<ctx_grid, 256>>>(sc, v, ctx);
        conv_split(ctx, ah, al, XN);
        mm_gemm(ah, al, wh + OFF_O1 + lp, wl + OFF_O1 + lp, tmp, ROWS, DMODEL, DMODEL, 0);
        add_ln_kernel<<<ROWS, 256>>>(tmp, x, g1 + i * DMODEL, b1 + i * DMODEL, x);

        // ---- MHA2 (unmasked; attn saved) ----
        conv_split(x, ah, al, XN);
        mm_gemm(ah, al, wh + OFF_Q2 + lp, wl + OFF_Q2 + lp, q, ROWS, DMODEL, DMODEL, 0);
        mm_gemm(ah, al, wh + OFF_K2 + lp, wl + OFF_K2 + lp, k, ROWS, DMODEL, DMODEL, 0);
        mm_gemm(ah, al, wh + OFF_V2 + lp, wl + OFF_V2 + lp, v, ROWS, DMODEL, DMODEL, 0);
        attn_scores_kernel<<<sc_grid, 256>>>(q, k, sc);
        softmax_kernel<<<BH * SEQ, 128>>>(sc, dec, 0);
        cudaMemcpyAsync(out + XN + (size_t)i * ATTN_SZ, sc,
                        ATTN_SZ * sizeof(float), cudaMemcpyDeviceToDevice, 0);
        attn_ctx_kernel<<<ctx_grid, 256>>>(sc, v, ctx);
        conv_split(ctx, ah, al, XN);
        mm_gemm(ah, al, wh + OFF_O2 + lp, wl + OFF_O2 + lp, tmp, ROWS, DMODEL, DMODEL, 0);
        add_ln_kernel<<<ROWS, 256>>>(tmp, x, g2 + i * DMODEL, b2 + i * DMODEL, x);

        // ---- FFN ----
        conv_split(x, ah, al, XN);
        mm_gemm(ah, al, wh + OFF_F1 + lf, wl + OFF_F1 + lf, ffn, ROWS, DFF, DMODEL, 1);
        conv_split(ffn, ah, al, (size_t)ROWS * DFF);
        mm_gemm(ah, al, wh + OFF_F2 + lf, wl + OFF_F2 + lf, tmp, ROWS, DMODEL, DFF, 0);
        add_ln_kernel<<<ROWS, 256>>>(tmp, x, gff + i * DMODEL, bff + i * DMODEL, x);
    }

    cudaMemcpyAsync(out, x, XN * sizeof(float), cudaMemcpyDeviceToDevice, 0);
}

// round 5
// speedup vs baseline: 2.9758x; 1.3156x over previous
#include <cuda_runtime.h>
#include <cuda_bf16.h>
#include <cstdint>
#include <cstddef>

// ---------------------------------------------------------------------------
// Problem dims (fixed)
// ---------------------------------------------------------------------------
#define LAYERS 6
#define BATCH  4
#define SEQ    512
#define DMODEL 1024
#define NHEAD  16
#define DHEAD  64
#define DFF    4096
#define ROWS   (BATCH * SEQ)           // 2048
#define BH     (BATCH * NHEAD)         // 64
#define QKVN   (3 * DMODEL)            // 3072

// ---------------------------------------------------------------------------
// Scratch (device globals; no allocation allowed)
// ---------------------------------------------------------------------------
__device__ float g_x  [ROWS * DMODEL];
__device__ float g_tmp[ROWS * DMODEL];
__device__ float g_sc [(size_t)BH * SEQ * SEQ];

__device__ __nv_bfloat16 g_xh  [ROWS * DMODEL];
__device__ __nv_bfloat16 g_xl  [ROWS * DMODEL];
__device__ __nv_bfloat16 g_qkvh[(size_t)ROWS * QKVN];
__device__ __nv_bfloat16 g_qkvl[(size_t)ROWS * QKVN];
__device__ __nv_bfloat16 g_ctxh[ROWS * DMODEL];
__device__ __nv_bfloat16 g_ctxl[ROWS * DMODEL];
__device__ __nv_bfloat16 g_fh  [(size_t)ROWS * DFF];
__device__ __nv_bfloat16 g_fl  [(size_t)ROWS * DFF];
__device__ __nv_bfloat16 g_ph  [(size_t)BH * SEQ * SEQ];
__device__ __nv_bfloat16 g_pl  [(size_t)BH * SEQ * SEQ];

#define MEG (1024 * 1024)
#define W_TOTAL ((size_t)96 * MEG)
__device__ __nv_bfloat16 g_wh[W_TOTAL];
__device__ __nv_bfloat16 g_wl[W_TOTAL];

// weight offsets (elements)
#define OFF_QKV1 ((size_t)0 * MEG)    // 6 layers x 3M (Q|K|V stacked [3072,1024])
#define OFF_O1   ((size_t)18 * MEG)   // 6 x 1M
#define OFF_QKV2 ((size_t)24 * MEG)   // 6 x 3M
#define OFF_O2   ((size_t)42 * MEG)   // 6 x 1M
#define OFF_F1   ((size_t)48 * MEG)   // 6 x 4M  [4096,1024]
#define OFF_F2   ((size_t)72 * MEG)   // 6 x 4M  [1024,4096]

// ---------------------------------------------------------------------------
// PTX helpers (arch-neutral: cp.async / ldmatrix / mma.sync)
// ---------------------------------------------------------------------------
__device__ __forceinline__ uint32_t smem_u32(const void* p) {
    uint32_t a;
    asm("{ .reg .u64 t; cvta.to.shared.u64 t, %1; cvt.u32.u64 %0, t; }"
        : "=r"(a) : "l"(p));
    return a;
}
__device__ __forceinline__ void cp16(uint32_t dst, const void* src) {
    asm volatile("cp.async.cg.shared.global [%0], [%1], 16;"
                 :: "r"(dst), "l"(src) : "memory");
}
#define CP_COMMIT() asm volatile("cp.async.commit_group;" ::: "memory")
#define CP_WAIT(n)  asm volatile("cp.async.wait_group %0;" :: "n"(n) : "memory")

__device__ __forceinline__ void ldsm_x4(uint32_t a[4], uint32_t addr) {
    asm volatile("ldmatrix.sync.aligned.m8n8.x4.shared.b16 {%0,%1,%2,%3}, [%4];"
                 : "=r"(a[0]), "=r"(a[1]), "=r"(a[2]), "=r"(a[3]) : "r"(addr));
}
__device__ __forceinline__ void ldsm_x2(uint32_t a[2], uint32_t addr) {
    asm volatile("ldmatrix.sync.aligned.m8n8.x2.shared.b16 {%0,%1}, [%2];"
                 : "=r"(a[0]), "=r"(a[1]) : "r"(addr));
}
__device__ __forceinline__ void ldsm_x2t(uint32_t a[2], uint32_t addr) {
    asm volatile("ldmatrix.sync.aligned.m8n8.x2.trans.shared.b16 {%0,%1}, [%2];"
                 : "=r"(a[0]), "=r"(a[1]) : "r"(addr));
}
__device__ __forceinline__ void mma_bf16(float c[4], const uint32_t a[4],
                                         const uint32_t b[2]) {
    asm volatile("mma.sync.aligned.m16n8k16.row.col.f32.bf16.bf16.f32 "
                 "{%0,%1,%2,%3}, {%4,%5,%6,%7}, {%8,%9}, {%0,%1,%2,%3};"
                 : "+f"(c[0]), "+f"(c[1]), "+f"(c[2]), "+f"(c[3])
                 : "r"(a[0]), "r"(a[1]), "r"(a[2]), "r"(a[3]),
                   "r"(b[0]), "r"(b[1]));
}
__device__ __forceinline__ void store_split2(__nv_bfloat16* H, __nv_bfloat16* L,
                                             size_t off, float a, float b) {
    __nv_bfloat16 ha = __float2bfloat16_rn(a), hb = __float2bfloat16_rn(b);
    __nv_bfloat16 la = __float2bfloat16_rn(a - __bfloat162float(ha));
    __nv_bfloat16 lb = __float2bfloat16_rn(b - __bfloat162float(hb));
    __nv_bfloat162 hv; hv.x = ha; hv.y = hb;
    __nv_bfloat162 lv; lv.x = la; lv.y = lb;
    *(__nv_bfloat162*)(H + off) = hv;
    *(__nv_bfloat162*)(L + off) = lv;
}

// ---------------------------------------------------------------------------
// Main GEMM: C[M,N] = (Ah+Al)[M,K] @ (Bh+Bl)[N,K]^T   (3-term bf16 split)
// 128x128x32 tiles, 256 threads, 4-stage cp.async, one barrier per chunk.
// Epilogue: optional fp32 out (Cf), optional bf16 hi/lo out (Ch/Cl), relu.
// ---------------------------------------------------------------------------
#define BKC      32
#define APITCH   80
#define TILE_B   (128 * APITCH)        // 10240
#define STG_B    (4 * TILE_B)          // 40960
#define NSTAGE   4
#define GEMM_SMEM (NSTAGE * STG_B)     // 163840

#define OFF_TAH 0
#define OFF_TAL TILE_B
#define OFF_TBH (2 * TILE_B)
#define OFF_TBL (3 * TILE_B)

__global__ void __launch_bounds__(256, 1)
mm_gemm_kernel(const __nv_bfloat16* __restrict__ Ah,
               const __nv_bfloat16* __restrict__ Al,
               const __nv_bfloat16* __restrict__ Bh,
               const __nv_bfloat16* __restrict__ Bl,
               float* __restrict__ Cf,
               __nv_bfloat16* __restrict__ Ch, __nv_bfloat16* __restrict__ Cl,
               int M, int N, int K, int relu)
{
    extern __shared__ char smem[];
    const uint32_t sb = smem_u32(smem);
    const int tid  = threadIdx.x;
    const int wid  = tid >> 5, lane = tid & 31;
    const int wm   = wid >> 2;
    const int wn   = wid & 3;
    const int m0   = blockIdx.y * 128, n0 = blockIdx.x * 128;

    const int r0 = tid >> 1;
    const int c0 = (tid & 1) * 2;

    float acc[4][4][4];
    #pragma unroll
    for (int i = 0; i < 4; ++i)
        #pragma unroll
        for (int j = 0; j < 4; ++j)
            #pragma unroll
            for (int t = 0; t < 4; ++t) acc[i][j][t] = 0.f;

    const int NCHUNK = K / BKC;

    auto load_stage = [&](int stage, int chunk) {
        const uint32_t st = sb + stage * STG_B;
        const int k0 = chunk * BKC;
        #pragma unroll
        for (int u = 0; u < 2; ++u) {
            const int c = c0 + u;
            const uint32_t so = (uint32_t)(r0 * APITCH + c * 16);
            const size_t   ga = (size_t)(m0 + r0) * K + k0 + c * 8;
            const size_t   gb = (size_t)(n0 + r0) * K + k0 + c * 8;
            cp16(st + OFF_TAH + so, Ah + ga);
            cp16(st + OFF_TAL + so, Al + ga);
            cp16(st + OFF_TBH + so, Bh + gb);
            cp16(st + OFF_TBL + so, Bl + gb);
        }
    };

    #pragma unroll
    for (int s = 0; s < NSTAGE - 1; ++s) {
        if (s < NCHUNK) load_stage(s, s);
        CP_COMMIT();
    }

    for (int ch = 0; ch < NCHUNK; ++ch) {
        CP_WAIT(NSTAGE - 2);
        __syncthreads();

        if (ch + NSTAGE - 1 < NCHUNK)
            load_stage((ch + NSTAGE - 1) % NSTAGE, ch + NSTAGE - 1);
        CP_COMMIT();

        const uint32_t st  = sb + (ch % NSTAGE) * STG_B;
        const uint32_t bAh = st + OFF_TAH, bBh = st + OFF_TBH;

        #pragma unroll
        for (int ks = 0; ks < 2; ++ks) {
            const int kb = ks * 32;
            uint32_t fbh[4][2], fbl[4][2];
            #pragma unroll
            for (int nt = 0; nt < 4; ++nt) {
                uint32_t addr = bBh
                    + (uint32_t)((wn * 32 + nt * 8 + (lane & 7)) * APITCH
                                 + kb + ((lane >> 3) & 1) * 16);
                ldsm_x2(fbh[nt], addr);
                ldsm_x2(fbl[nt], addr + TILE_B);
            }
            #pragma unroll
            for (int mt = 0; mt < 4; ++mt) {
                uint32_t addr = bAh
                    + (uint32_t)((wm * 64 + mt * 16 + (lane & 15)) * APITCH
                                 + kb + (lane >> 4) * 16);
                uint32_t fah[4], fal[4];
                ldsm_x4(fah, addr);
                ldsm_x4(fal, addr + TILE_B);
                #pragma unroll
                for (int nt = 0; nt < 4; ++nt) {
                    mma_bf16(acc[mt][nt], fah, fbh[nt]);
                    mma_bf16(acc[mt][nt], fah, fbl[nt]);
                    mma_bf16(acc[mt][nt], fal, fbh[nt]);
                }
            }
        }
    }

    const int rbase = m0 + wm * 64 + (lane >> 2);
    const int cbase = n0 + wn * 32 + (lane & 3) * 2;
    #pragma unroll
    for (int mt = 0; mt < 4; ++mt) {
        #pragma unroll
        for (int nt = 0; nt < 4; ++nt) {
            float* c = acc[mt][nt];
            if (relu) {
                c[0] = fmaxf(c[0], 0.f); c[1] = fmaxf(c[1], 0.f);
                c[2] = fmaxf(c[2], 0.f); c[3] = fmaxf(c[3], 0.f);
            }
            const int rr = rbase + mt * 16;
            const int cc = cbase + nt * 8;
            if (Cf) {
                *(float2*)(Cf + (size_t)rr * N + cc)       = make_float2(c[0], c[1]);
                *(float2*)(Cf + (size_t)(rr + 8) * N + cc) = make_float2(c[2], c[3]);
            }
            if (Ch) {
                store_split2(Ch, Cl, (size_t)rr * N + cc,       c[0], c[1]);
                store_split2(Ch, Cl, (size_t)(rr + 8) * N + cc, c[2], c[3]);
            }
        }
    }
}

// ---------------------------------------------------------------------------
// Attention scores (tensor): sc[bh,q,k] = (Q.K)/8, 3-term split.
// CTA: 128q x 128k, K=64 single stage. Skips fully-masked tiles.
// qkv layout: [row, 3072] with Q at 0, K at 1024, V at 2048 (+h*64).
// ---------------------------------------------------------------------------
#define SPITCH 144
#define STILE  (128 * SPITCH)          // 18432
#define SC_SMEM (4 * STILE)            // 73728

__global__ void __launch_bounds__(256)
attn_score_kernel(const __nv_bfloat16* __restrict__ QKVh,
                  const __nv_bfloat16* __restrict__ QKVl,
                  float* __restrict__ sc, int masked)
{
    const int bh = blockIdx.z, b = bh >> 4, h = bh & 15;
    const int q0 = blockIdx.y * 128, k0 = blockIdx.x * 128;
    if (masked && k0 >= q0 + 128) return;   // fully masked tile

    extern __shared__ char smem[];
    const uint32_t sb = smem_u32(smem);
    const int tid = threadIdx.x;
    const int wid = tid >> 5, lane = tid & 31;
    const int wm = wid >> 2, wn = wid & 3;

    {
        const int r  = tid >> 1;
        const int cb = (tid & 1) * 4;
        #pragma unroll
        for (int u = 0; u < 4; ++u) {
            const int c = cb + u;
            const uint32_t so = (uint32_t)(r * SPITCH + c * 16);
            const size_t gq = (size_t)(b * SEQ + q0 + r) * QKVN + h * DHEAD + c * 8;
            const size_t gk = (size_t)(b * SEQ + k0 + r) * QKVN + DMODEL + h * DHEAD + c * 8;
            cp16(sb + 0 * STILE + so, QKVh + gq);
            cp16(sb + 1 * STILE + so, QKVl + gq);
            cp16(sb + 2 * STILE + so, QKVh + gk);
            cp16(sb + 3 * STILE + so, QKVl + gk);
        }
    }
    CP_COMMIT();
    CP_WAIT(0);
    __syncthreads();

    float acc[4][4][4];
    #pragma unroll
    for (int i = 0; i < 4; ++i)
        #pragma unroll
        for (int j = 0; j < 4; ++j)
            #pragma unroll
            for (int t = 0; t < 4; ++t) acc[i][j][t] = 0.f;

    #pragma unroll
    for (int ks = 0; ks < 4; ++ks) {
        const int kb = ks * 32;
        uint32_t fbh[4][2], fbl[4][2];
        #pragma unroll
        for (int nt = 0; nt < 4; ++nt) {
            uint32_t addr = sb + 2 * STILE
                + (uint32_t)((wn * 32 + nt * 8 + (lane & 7)) * SPITCH
                             + kb + ((lane >> 3) & 1) * 16);
            ldsm_x2(fbh[nt], addr);
            ldsm_x2(fbl[nt], addr + STILE);
        }
        #pragma unroll
        for (int mt = 0; mt < 4; ++mt) {
            uint32_t addr = sb
                + (uint32_t)((wm * 64 + mt * 16 + (lane & 15)) * SPITCH
                             + kb + (lane >> 4) * 16);
            uint32_t fah[4], fal[4];
            ldsm_x4(fah, addr);
            ldsm_x4(fal, addr + STILE);
            #pragma unroll
            for (int nt = 0; nt < 4; ++nt) {
                mma_bf16(acc[mt][nt], fah, fbh[nt]);
                mma_bf16(acc[mt][nt], fah, fbl[nt]);
                mma_bf16(acc[mt][nt], fal, fbh[nt]);
            }
        }
    }

    float* S = sc + (size_t)bh * SEQ * SEQ;
    const int rbase = q0 + wm * 64 + (lane >> 2);
    const int cbase = k0 + wn * 32 + (lane & 3) * 2;
    #pragma unroll
    for (int mt = 0; mt < 4; ++mt) {
        #pragma unroll
        for (int nt = 0; nt < 4; ++nt) {
            const float* c = acc[mt][nt];
            const int rr = rbase + mt * 16;
            const int cc = cbase + nt * 8;
            *(float2*)(S + (size_t)rr * SEQ + cc) =
                make_float2(c[0] * 0.125f, c[1] * 0.125f);
            *(float2*)(S + (size_t)(rr + 8) * SEQ + cc) =
                make_float2(c[2] * 0.125f, c[3] * 0.125f);
        }
    }
}

// ---------------------------------------------------------------------------
// Softmax: reads fp32 scores, applies mask, writes P hi/lo bf16 and
// (optionally) fp32 probs straight to the output tensor.
// ---------------------------------------------------------------------------
__device__ __forceinline__ float block_reduce_sum(float v, float* shm) {
    __syncthreads();
    int lane = threadIdx.x & 31, w = threadIdx.x >> 5;
    #pragma unroll
    for (int o = 16; o; o >>= 1) v += __shfl_xor_sync(0xffffffff, v, o);
    if (lane == 0) shm[w] = v;
    __syncthreads();
    int nw = blockDim.x >> 5;
    float r = (threadIdx.x < nw) ? shm[threadIdx.x] : 0.f;
    if (w == 0) {
        #pragma unroll
        for (int o = 16; o; o >>= 1) r += __shfl_xor_sync(0xffffffff, r, o);
        if (lane == 0) shm[0] = r;
    }
    __syncthreads();
    return shm[0];
}
__device__ __forceinline__ float block_reduce_max(float v, float* shm) {
    __syncthreads();
    int lane = threadIdx.x & 31, w = threadIdx.x >> 5;
    #pragma unroll
    for (int o = 16; o; o >>= 1) v = fmaxf(v, __shfl_xor_sync(0xffffffff, v, o));
    if (lane == 0) shm[w] = v;
    __syncthreads();
    int nw = blockDim.x >> 5;
    float r = (threadIdx.x < nw) ? shm[threadIdx.x] : -3.4e38f;
    if (w == 0) {
        #pragma unroll
        for (int o = 16; o; o >>= 1) r = fmaxf(r, __shfl_xor_sync(0xffffffff, r, o));
        if (lane == 0) shm[0] = r;
    }
    __syncthreads();
    return shm[0];
}

__global__ void __launch_bounds__(128) softmax_kernel(
    const float* __restrict__ scores, const int* __restrict__ dec, int masked,
    __nv_bfloat16* __restrict__ Ph, __nv_bfloat16* __restrict__ Pl,
    float* __restrict__ outp)
{
    __shared__ float shm[32];
    const int row = blockIdx.x;            // bh*SEQ + q
    const int q   = row & (SEQ - 1);
    const int bh  = row >> 9;
    const int b   = bh >> 4;
    const float* S = scores + (size_t)row * SEQ;
    const int* db = dec + b * SEQ;

    float v[4];
    float mx = -3.4e38f;
    #pragma unroll
    for (int u = 0; u < 4; ++u) {
        int k = threadIdx.x + u * 128;
        float s = S[k];
        if (masked && ((k > q) || (db[k] == 0))) s = -1e9f;
        v[u] = s;
        mx = fmaxf(mx, s);
    }
    mx = block_reduce_max(mx, shm);

    float sum = 0.f;
    #pragma unroll
    for (int u = 0; u < 4; ++u) {
        v[u] = expf(v[u] - mx);
        sum += v[u];
    }
    sum = block_reduce_sum(sum, shm);
    const float inv = 1.f / sum;

    #pragma unroll
    for (int u = 0; u < 4; ++u) {
        int k = threadIdx.x + u * 128;
        float p = v[u] * inv;
        __nv_bfloat16 h = __float2bfloat16_rn(p);
        __nv_bfloat16 l = __float2bfloat16_rn(p - __bfloat162float(h));
        Ph[(size_t)row * SEQ + k] = h;
        Pl[(size_t)row * SEQ + k] = l;
        if (outp) outp[(size_t)row * SEQ + k] = p;
    }
}

// ---------------------------------------------------------------------------
// ctx (tensor): ctx[b,q,h*64+d] = sum_k P[bh,q,k] * V[b,k,h*64+d], 3-term.
// CTA: 128q x 64d, K=512 in 16 chunks of 32, 4-stage pipeline.
// Epilogue writes bf16 hi/lo directly (feeds Wo GEMM).
// ---------------------------------------------------------------------------
#define PPITCH 80
#define PTILE  (128 * PPITCH)          // 10240
#define VPITCH 144
#define VTILE  (32 * VPITCH)           // 4608
#define CTX_STG (2 * PTILE + 2 * VTILE) // 29696
#define CTX_NST 4
#define CTX_SMEM (CTX_NST * CTX_STG)   // 118784

__global__ void __launch_bounds__(256, 1)
attn_ctx_kernel(const __nv_bfloat16* __restrict__ Ph,
                const __nv_bfloat16* __restrict__ Pl,
                const __nv_bfloat16* __restrict__ QKVh,
                const __nv_bfloat16* __restrict__ QKVl,
                __nv_bfloat16* __restrict__ Ch, __nv_bfloat16* __restrict__ Cl)
{
    const int bh = blockIdx.y, b = bh >> 4, h = bh & 15;
    const int q0 = blockIdx.x * 128;

    extern __shared__ char smem[];
    const uint32_t sb = smem_u32(smem);
    const int tid = threadIdx.x;
    const int wid = tid >> 5, lane = tid & 31;
    const int wm = wid >> 2, wn = wid & 3;

    const __nv_bfloat16* Pbh = Ph + (size_t)bh * SEQ * SEQ;
    const __nv_bfloat16* Pbl = Pl + (size_t)bh * SEQ * SEQ;

    float acc[4][2][4];
    #pragma unroll
    for (int i = 0; i < 4; ++i)
        #pragma unroll
        for (int j = 0; j < 2; ++j)
            #pragma unroll
            for (int t = 0; t < 4; ++t) acc[i][j][t] = 0.f;

    auto load_stage = [&](int stage, int chunk) {
        const uint32_t st = sb + stage * CTX_STG;
        const int k0 = chunk * 32;
        // P tiles: 128 rows x 64B (2 chunks/thread)
        {
            const int r  = tid >> 1;
            const int cb = (tid & 1) * 2;
            #pragma unroll
            for (int u = 0; u < 2; ++u) {
                const int c = cb + u;
                const uint32_t so = (uint32_t)(r * PPITCH + c * 16);
                const size_t gp = (size_t)(q0 + r) * SEQ + k0 + c * 8;
                cp16(st + so,         Pbh + gp);
                cp16(st + PTILE + so, Pbl + gp);
            }
        }
        // V tiles: 32 rows x 128B (1 chunk/thread)
        {
            const int r = tid >> 3, c = tid & 7;
            const uint32_t so = (uint32_t)(r * VPITCH + c * 16);
            const size_t gv = (size_t)(b * SEQ + k0 + r) * QKVN
                            + 2 * DMODEL + h * DHEAD + c * 8;
            cp16(st + 2 * PTILE + so,         QKVh + gv);
            cp16(st + 2 * PTILE + VTILE + so, QKVl + gv);
        }
    };

    const int NCHUNK = SEQ / 32;   // 16
    #pragma unroll
    for (int s = 0; s < CTX_NST - 1; ++s) {
        load_stage(s, s);
        CP_COMMIT();
    }

    for (int ch = 0; ch < NCHUNK; ++ch) {
        CP_WAIT(CTX_NST - 2);
        __syncthreads();
        if (ch + CTX_NST - 1 < NCHUNK)
            load_stage((ch + CTX_NST - 1) % CTX_NST, ch + CTX_NST - 1);
        CP_COMMIT();

        const uint32_t st  = sb + (ch % CTX_NST) * CTX_STG;
        const uint32_t bP  = st;
        const uint32_t bV  = st + 2 * PTILE;

        #pragma unroll
        for (int ks = 0; ks < 2; ++ks) {
            const int kb = ks * 32;   // bytes into P rows
            uint32_t fbh[2][2], fbl[2][2];
            #pragma unroll
            for (int nt = 0; nt < 2; ++nt) {
                uint32_t addr = bV
                    + (uint32_t)((ks * 16 + (lane & 15)) * VPITCH
                                 + (wn * 16 + nt * 8) * 2);
                ldsm_x2t(fbh[nt], addr);
                ldsm_x2t(fbl[nt], addr + VTILE);
            }
            #pragma unroll
            for (int mt = 0; mt < 4; ++mt) {
                uint32_t addr = bP
                    + (uint32_t)((wm * 64 + mt * 16 + (lane & 15)) * PPITCH
                                 + kb + (lane >> 4) * 16);
                uint32_t fah[4], fal[4];
                ldsm_x4(fah, addr);
                ldsm_x4(fal, addr + PTILE);
                #pragma unroll
                for (int nt = 0; nt < 2; ++nt) {
                    mma_bf16(acc[mt][nt], fah, fbh[nt]);
                    mma_bf16(acc[mt][nt], fah, fbl[nt]);
                    mma_bf16(acc[mt][nt], fal, fbh[nt]);
                }
            }
        }
    }

    const int rbase = b * SEQ + q0 + wm * 64 + (lane >> 2);
    const int cbase = h * DHEAD + wn * 16 + (lane & 3) * 2;
    #pragma unroll
    for (int mt = 0; mt < 4; ++mt) {
        #pragma unroll
        for (int nt = 0; nt < 2; ++nt) {
            const float* c = acc[mt][nt];
            const int rr = rbase + mt * 16;
            const int cc = cbase + nt * 8;
            store_split2(Ch, Cl, (size_t)rr * DMODEL + cc,       c[0], c[1]);
            store_split2(Ch, Cl, (size_t)(rr + 8) * DMODEL + cc, c[2], c[3]);
        }
    }
}

// ---------------------------------------------------------------------------
// Weight transpose + split: W[l][K][N] fp32 -> out[l][N][K] bf16 hi/lo
// separate src/dst layer strides (for QKV packing).
// ---------------------------------------------------------------------------
__global__ void __launch_bounds__(256) convT_split_kernel(
    const float* __restrict__ W, __nv_bfloat16* __restrict__ H,
    __nv_bfloat16* __restrict__ L, int K, int N,
    size_t srcStride, size_t dstStride)
{
    __shared__ float t[32][33];
    const float* Wl = W + (size_t)blockIdx.z * srcStride;
    const size_t dofs = (size_t)blockIdx.z * dstStride;
    const int n0 = blockIdx.x * 32, k0 = blockIdx.y * 32;
    const int tx = threadIdx.x, ty = threadIdx.y;
    #pragma unroll
    for (int i = 0; i < 32; i += 8)
        t[ty + i][tx] = Wl[(size_t)(k0 + ty + i) * N + n0 + tx];
    __syncthreads();
    #pragma unroll
    for (int i = 0; i < 32; i += 8) {
        float v = t[tx][ty + i];
        __nv_bfloat16 h = __float2bfloat16_rn(v);
        __nv_bfloat16 l = __float2bfloat16_rn(v - __bfloat162float(h));
        size_t o = dofs + (size_t)(n0 + ty + i) * K + k0 + tx;
        H[o] = h; L[o] = l;
    }
}

// ---------------------------------------------------------------------------
// Embedding (writes fp32 + bf16 splits)
// ---------------------------------------------------------------------------
__global__ void embed_kernel(const int* __restrict__ dec,
                             const float* __restrict__ tok,
                             const float* __restrict__ pos,
                             float* __restrict__ x,
                             __nv_bfloat16* __restrict__ xh,
                             __nv_bfloat16* __restrict__ xl) {
    int row = blockIdx.x;
    int s   = row & (SEQ - 1);
    int t   = dec[row];
    const float* tp = tok + (size_t)t * DMODEL;
    const float* pp = pos + (size_t)s * DMODEL;
    size_t base = (size_t)row * DMODEL;
    #pragma unroll
    for (int u = 0; u < 4; ++u) {
        int c = threadIdx.x + u * 256;
        float v = tp[c] + pp[c];
        x[base + c] = v;
        __nv_bfloat16 h = __float2bfloat16_rn(v);
        xh[base + c] = h;
        xl[base + c] = __float2bfloat16_rn(v - __bfloat162float(h));
    }
}

// ---------------------------------------------------------------------------
// out = LayerNorm(a + r) * g + beta  (writes fp32 + bf16 splits)
// ---------------------------------------------------------------------------
__global__ void __launch_bounds__(256) add_ln_kernel(
    const float* __restrict__ a, const float* __restrict__ r,
    const float* __restrict__ g, const float* __restrict__ beta,
    float* __restrict__ out,
    __nv_bfloat16* __restrict__ oh, __nv_bfloat16* __restrict__ ol)
{
    __shared__ float shm[32];
    int row = blockIdx.x;
    const float* ap = a + (size_t)row * DMODEL;
    const float* rp = r + (size_t)row * DMODEL;
    size_t base = (size_t)row * DMODEL;

    float v[4];
    float s = 0.f;
    #pragma unroll
    for (int u = 0; u < 4; ++u) {
        int c = threadIdx.x + u * 256;
        v[u] = ap[c] + rp[c];
        s += v[u];
    }
    float mean = block_reduce_sum(s, shm) * (1.f / DMODEL);

    float sq = 0.f;
    #pragma unroll
    for (int u = 0; u < 4; ++u) {
        float d = v[u] - mean;
        sq += d * d;
    }
    float var = block_reduce_sum(sq, shm) * (1.f / DMODEL);
    float rstd = rsqrtf(var + 1e-5f);

    #pragma unroll
    for (int u = 0; u < 4; ++u) {
        int c = threadIdx.x + u * 256;
        float o = (v[u] - mean) * rstd * g[c] + beta[c];
        out[base + c] = o;
        __nv_bfloat16 h = __float2bfloat16_rn(o);
        oh[base + c] = h;
        ol[base + c] = __float2bfloat16_rn(o - __bfloat162float(h));
    }
}

// ---------------------------------------------------------------------------
// Host orchestration
// ---------------------------------------------------------------------------
static void mm_gemm(const __nv_bfloat16* ah, const __nv_bfloat16* al,
                    const __nv_bfloat16* bh, const __nv_bfloat16* bl,
                    float* Cf, __nv_bfloat16* Ch, __nv_bfloat16* Cl,
                    int M, int N, int K, int relu) {
    dim3 grid(N / 128, M / 128);
    mm_gemm_kernel<<<grid, 256, GEMM_SMEM>>>(ah, al, bh, bl, Cf, Ch, Cl,
                                             M, N, K, relu);
}

extern "C" void kernel_launch(void* const* d_in, const int* in_sizes, int n_in,
                              void* d_out, int out_size) {
    const int*   dec  = (const int*)  d_in[0];
    const float* tok  = (const float*)d_in[1];
    const float* pos  = (const float*)d_in[2];
    const float* Wq1  = (const float*)d_in[3];
    const float* Wk1  = (const float*)d_in[4];
    const float* Wv1  = (const float*)d_in[5];
    const float* Wo1  = (const float*)d_in[6];
    const float* g1   = (const float*)d_in[7];
    const float* b1   = (const float*)d_in[8];
    const float* Wq2  = (const float*)d_in[9];
    const float* Wk2  = (const float*)d_in[10];
    const float* Wv2  = (const float*)d_in[11];
    const float* Wo2  = (const float*)d_in[12];
    const float* g2   = (const float*)d_in[13];
    const float* b2   = (const float*)d_in[14];
    const float* Wff1 = (const float*)d_in[15];
    const float* Wff2 = (const float*)d_in[16];
    const float* gff  = (const float*)d_in[17];
    const float* bff  = (const float*)d_in[18];
    float* out = (float*)d_out;

    cudaFuncSetAttribute(mm_gemm_kernel,
                         cudaFuncAttributeMaxDynamicSharedMemorySize, GEMM_SMEM);
    cudaFuncSetAttribute(attn_score_kernel,
                         cudaFuncAttributeMaxDynamicSharedMemorySize, SC_SMEM);
    cudaFuncSetAttribute(attn_ctx_kernel,
                         cudaFuncAttributeMaxDynamicSharedMemorySize, CTX_SMEM);

    float *x, *tmp, *sc;
    __nv_bfloat16 *xh, *xl, *qkvh, *qkvl, *ctxh, *ctxl, *fh, *fl, *ph, *pl, *wh, *wl;
    cudaGetSymbolAddress((void**)&x,    g_x);
    cudaGetSymbolAddress((void**)&tmp,  g_tmp);
    cudaGetSymbolAddress((void**)&sc,   g_sc);
    cudaGetSymbolAddress((void**)&xh,   g_xh);
    cudaGetSymbolAddress((void**)&xl,   g_xl);
    cudaGetSymbolAddress((void**)&qkvh, g_qkvh);
    cudaGetSymbolAddress((void**)&qkvl, g_qkvl);
    cudaGetSymbolAddress((void**)&ctxh, g_ctxh);
    cudaGetSymbolAddress((void**)&ctxl, g_ctxl);
    cudaGetSymbolAddress((void**)&fh,   g_fh);
    cudaGetSymbolAddress((void**)&fl,   g_fl);
    cudaGetSymbolAddress((void**)&ph,   g_ph);
    cudaGetSymbolAddress((void**)&pl,   g_pl);
    cudaGetSymbolAddress((void**)&wh,   g_wh);
    cudaGetSymbolAddress((void**)&wl,   g_wl);

    // ---- weight prep: transpose + split; QKV packed [3072,1024] ----
    dim3 tb(32, 8);
    dim3 gp(32, 32, LAYERS);
    convT_split_kernel<<<gp, tb>>>(Wq1, wh + OFF_QKV1 + 0 * MEG, wl + OFF_QKV1 + 0 * MEG, 1024, 1024, MEG, 3 * MEG);
    convT_split_kernel<<<gp, tb>>>(Wk1, wh + OFF_QKV1 + 1 * MEG, wl + OFF_QKV1 + 1 * MEG, 1024, 1024, MEG, 3 * MEG);
    convT_split_kernel<<<gp, tb>>>(Wv1, wh + OFF_QKV1 + 2 * MEG, wl + OFF_QKV1 + 2 * MEG, 1024, 1024, MEG, 3 * MEG);
    convT_split_kernel<<<gp, tb>>>(Wo1, wh + OFF_O1, wl + OFF_O1, 1024, 1024, MEG, MEG);
    convT_split_kernel<<<gp, tb>>>(Wq2, wh + OFF_QKV2 + 0 * MEG, wl + OFF_QKV2 + 0 * MEG, 1024, 1024, MEG, 3 * MEG);
    convT_split_kernel<<<gp, tb>>>(Wk2, wh + OFF_QKV2 + 1 * MEG, wl + OFF_QKV2 + 1 * MEG, 1024, 1024, MEG, 3 * MEG);
    convT_split_kernel<<<gp, tb>>>(Wv2, wh + OFF_QKV2 + 2 * MEG, wl + OFF_QKV2 + 2 * MEG, 1024, 1024, MEG, 3 * MEG);
    convT_split_kernel<<<gp, tb>>>(Wo2, wh + OFF_O2, wl + OFF_O2, 1024, 1024, MEG, MEG);
    convT_split_kernel<<<dim3(128, 32, LAYERS), tb>>>(Wff1, wh + OFF_F1, wl + OFF_F1, 1024, 4096, 4 * MEG, 4 * MEG);
    convT_split_kernel<<<dim3(32, 128, LAYERS), tb>>>(Wff2, wh + OFF_F2, wl + OFF_F2, 4096, 1024, 4 * MEG, 4 * MEG);

    const size_t ATTN_SZ = (size_t)BH * SEQ * SEQ;
    const size_t XN = (size_t)ROWS * DMODEL;

    embed_kernel<<<ROWS, 256>>>(dec, tok, pos, x, xh, xl);

    dim3 sc_grid(SEQ / 128, SEQ / 128, BH);
    dim3 ctx_grid(SEQ / 128, BH);

    for (int i = 0; i < LAYERS; ++i) {
        const size_t l1 = (size_t)i * MEG;
        const size_t l3 = (size_t)i * 3 * MEG;
        const size_t l4 = (size_t)i * 4 * MEG;

        // ---- MHA1 (masked) ----
        mm_gemm(xh, xl, wh + OFF_QKV1 + l3, wl + OFF_QKV1 + l3,
                nullptr, qkvh, qkvl, ROWS, QKVN, DMODEL, 0);
        attn_score_kernel<<<sc_grid, 256, SC_SMEM>>>(qkvh, qkvl, sc, 1);
        softmax_kernel<<<BH * SEQ, 128>>>(sc, dec, 1, ph, pl, nullptr);
        attn_ctx_kernel<<<ctx_grid, 256, CTX_SMEM>>>(ph, pl, qkvh, qkvl, ctxh, ctxl);
        mm_gemm(ctxh, ctxl, wh + OFF_O1 + l1, wl + OFF_O1 + l1,
                tmp, nullptr, nullptr, ROWS, DMODEL, DMODEL, 0);
        add_ln_kernel<<<ROWS, 256>>>(tmp, x, g1 + i * DMODEL, b1 + i * DMODEL, x, xh, xl);

        // ---- MHA2 (unmasked; probs -> out) ----
        mm_gemm(xh, xl, wh + OFF_QKV2 + l3, wl + OFF_QKV2 + l3,
                nullptr, qkvh, qkvl, ROWS, QKVN, DMODEL, 0);
        attn_score_kernel<<<sc_grid, 256, SC_SMEM>>>(qkvh, qkvl, sc, 0);
        softmax_kernel<<<BH * SEQ, 128>>>(sc, dec, 0, ph, pl,
                                          out + XN + (size_t)i * ATTN_SZ);
        attn_ctx_kernel<<<ctx_grid, 256, CTX_SMEM>>>(ph, pl, qkvh, qkvl, ctxh, ctxl);
        mm_gemm(ctxh, ctxl, wh + OFF_O2 + l1, wl + OFF_O2 + l1,
                tmp, nullptr, nullptr, ROWS, DMODEL, DMODEL, 0);
        add_ln_kernel<<<ROWS, 256>>>(tmp, x, g2 + i * DMODEL, b2 + i * DMODEL, x, xh, xl);

        // ---- FFN ----
        mm_gemm(xh, xl, wh + OFF_F1 + l4, wl + OFF_F1 + l4,
                nullptr, fh, fl, ROWS, DFF, DMODEL, 1);
        mm_gemm(fh, fl, wh + OFF_F2 + l4, wl + OFF_F2 + l4,
                tmp, nullptr, nullptr, ROWS, DMODEL, DFF, 0);
        add_ln_kernel<<<ROWS, 256>>>(tmp, x, gff + i * DMODEL, bff + i * DMODEL, x, xh, xl);
    }

    cudaMemcpyAsync(out, x, XN * sizeof(float), cudaMemcpyDeviceToDevice, 0);
}